// round 1
// baseline (speedup 1.0000x reference)
#include <cuda_runtime.h>
#include <cuda_bf16.h>

// Depthwise 3x3 lateral conv (center tap zeroed by mask) + residual add.
// x: [B,H,W,C] f32 NHWC, kernel: [3,3,C] f32, out: [B,H,W,C] f32.
// B=32, H=56, W=56, C=256. Vectorized float4 over channels.

#define BH 32
#define HH 56
#define WW 56
#define CC 256
#define CG (CC / 4)   // 64 float4 channel-groups per pixel

__global__ __launch_bounds__(256) void contour_kernel(
    const float4* __restrict__ x,
    const float4* __restrict__ k,
    float4* __restrict__ out)
{
    // tid = pixel_index * 64 + channel_group  (matches linear float4 index of x/out)
    const long long tid = (long long)blockIdx.x * blockDim.x + threadIdx.x;
    const int cg = (int)(tid & 63);
    const long long p = tid >> 6;               // pixel index in [0, B*H*W)
    const int w = (int)(p % WW);
    const int h = (int)((p / WW) % HH);

    // center load doubles as the residual term (mask zeroes the center weight)
    float4 acc = x[tid];

    #pragma unroll
    for (int dy = -1; dy <= 1; ++dy) {
        const int hh = h + dy;
        const bool hok = (hh >= 0) && (hh < HH);
        #pragma unroll
        for (int dx = -1; dx <= 1; ++dx) {
            if (dy == 0 && dx == 0) continue;   // center tap excluded
            const int ww = w + dx;
            if (hok && ww >= 0 && ww < WW) {
                const long long np = p + (long long)dy * WW + dx;
                const float4 xv = x[np * CG + cg];
                const float4 kv = __ldg(&k[((dy + 1) * 3 + (dx + 1)) * CG + cg]);
                acc.x = fmaf(xv.x, kv.x, acc.x);
                acc.y = fmaf(xv.y, kv.y, acc.y);
                acc.z = fmaf(xv.z, kv.z, acc.z);
                acc.w = fmaf(xv.w, kv.w, acc.w);
            }
        }
    }

    out[tid] = acc;
}

extern "C" void kernel_launch(void* const* d_in, const int* in_sizes, int n_in,
                              void* d_out, int out_size)
{
    const float4* x = (const float4*)d_in[0];     // [B,H,W,C] f32
    const float4* k = (const float4*)d_in[1];     // [3,3,C] f32
    float4* out = (float4*)d_out;

    const long long total_f4 = (long long)BH * HH * WW * CG;  // 6,422,528
    const int threads = 256;
    const long long blocks = total_f4 / threads;              // 25,088 (divides exactly)

    contour_kernel<<<(unsigned)blocks, threads>>>(x, k, out);
}

// round 2
// speedup vs baseline: 1.3416x; 1.3416x over previous
#include <cuda_runtime.h>
#include <cuda_bf16.h>

// Depthwise 3x3 lateral conv (center tap zeroed) + residual add.
// x: [B,H,W,C] f32 NHWC, kernel: [3,3,C] f32. B=32,H=56,W=56,C=256.
// Register-blocked: each thread computes a 4(h) x 2(w) strip for one
// float4 channel-group. 24 loads + 8 stores per 8 outputs (vs 10 per 1).

#define BH 32
#define HH 56
#define WW 56
#define CG 64          // 256 channels / 4 = float4 groups
#define RH 4
#define RW 2

__global__ __launch_bounds__(256) void contour_kernel(
    const float4* __restrict__ x,
    const float4* __restrict__ k,
    float4* __restrict__ out)
{
    const int gid = blockIdx.x * 256 + threadIdx.x;
    const int cg  = gid & (CG - 1);
    int t = gid >> 6;
    const int w2 = t % (WW / RW);  t /= (WW / RW);
    const int h4 = t % (HH / RH);
    const int b  = t / (HH / RH);
    const int w0 = w2 * RW;
    const int h0 = h4 * RH;

    // 9 per-channel weights in registers (center tap is handled as residual)
    float4 kv[9];
    #pragma unroll
    for (int i = 0; i < 9; ++i) kv[i] = __ldg(&k[i * CG + cg]);

    float4 acc[RH][RW];
    #pragma unroll
    for (int j = 0; j < RH; ++j)
        #pragma unroll
        for (int i = 0; i < RW; ++i)
            acc[j][i] = make_float4(0.f, 0.f, 0.f, 0.f);

    const long long pbase = (long long)b * HH * WW;   // pixel base for batch b

    #pragma unroll
    for (int rr = 0; rr < RH + 2; ++rr) {
        const int r = h0 - 1 + rr;
        if (r < 0 || r >= HH) continue;               // zero-pad rows

        // load the 4-wide column window for this input row
        float4 col[RW + 2];
        #pragma unroll
        for (int c = 0; c < RW + 2; ++c) {
            const int w = w0 - 1 + c;
            if (w >= 0 && w < WW)
                col[c] = x[(pbase + (long long)r * WW + w) * CG + cg];
            else
                col[c] = make_float4(0.f, 0.f, 0.f, 0.f);
        }

        // accumulate into every output row this input row touches.
        // dy = rr - 1 - j is a compile-time constant after unrolling.
        #pragma unroll
        for (int j = 0; j < RH; ++j) {
            const int dy = rr - 1 - j;
            if (dy < -1 || dy > 1) continue;          // compile-time prune
            #pragma unroll
            for (int i = 0; i < RW; ++i) {
                #pragma unroll
                for (int dx = -1; dx <= 1; ++dx) {
                    if (dy == 0 && dx == 0) {
                        // center tap weight is zero; residual add instead
                        acc[j][i].x += col[i + 1].x;
                        acc[j][i].y += col[i + 1].y;
                        acc[j][i].z += col[i + 1].z;
                        acc[j][i].w += col[i + 1].w;
                        continue;
                    }
                    const float4 xv = col[i + 1 + dx];
                    const float4 wv = kv[(dy + 1) * 3 + (dx + 1)];
                    acc[j][i].x = fmaf(xv.x, wv.x, acc[j][i].x);
                    acc[j][i].y = fmaf(xv.y, wv.y, acc[j][i].y);
                    acc[j][i].z = fmaf(xv.z, wv.z, acc[j][i].z);
                    acc[j][i].w = fmaf(xv.w, wv.w, acc[j][i].w);
                }
            }
        }
    }

    #pragma unroll
    for (int j = 0; j < RH; ++j)
        #pragma unroll
        for (int i = 0; i < RW; ++i)
            out[(pbase + (long long)(h0 + j) * WW + (w0 + i)) * CG + cg] = acc[j][i];
}

extern "C" void kernel_launch(void* const* d_in, const int* in_sizes, int n_in,
                              void* d_out, int out_size)
{
    const float4* x = (const float4*)d_in[0];
    const float4* k = (const float4*)d_in[1];
    float4* out = (float4*)d_out;

    // threads = B * (H/RH) * (W/RW) * CG = 32*14*28*64 = 802816
    const int total = BH * (HH / RH) * (WW / RW) * CG;
    const int threads = 256;
    contour_kernel<<<total / threads, threads>>>(x, k, out);
}

// round 3
// speedup vs baseline: 1.4035x; 1.0462x over previous
#include <cuda_runtime.h>
#include <cuda_bf16.h>

// Depthwise 3x3 lateral conv (center tap zeroed) + residual add.
// x: [B,H,W,C] f32 NHWC, kernel: [3,3,C] f32. B=32,H=56,W=56,C=256.
// Register-blocked 4(h) x 2(w) per thread, one float4 channel-group.
// All addressing is 32-bit with a single base index; every load/store
// uses a compile-time immediate offset. Boundary handling is branchless
// (predicated loads) so loads batch across row iterations.

#define BH 32
#define HH 56
#define WW 56
#define CG 64            // 256 channels / 4
#define RH 4
#define RW 2
#define ROWS (WW * CG)   // float4 elements per image row = 3584

__global__ __launch_bounds__(256) void contour_kernel(
    const float4* __restrict__ x,
    const float4* __restrict__ k,
    float4* __restrict__ out)
{
    const int gid = blockIdx.x * 256 + threadIdx.x;
    const int cg  = gid & (CG - 1);
    int t = gid >> 6;
    const int w2 = t % (WW / RW);  t /= (WW / RW);
    const int h4 = t % (HH / RH);
    const int b  = t / (HH / RH);
    const int w0 = w2 * RW;
    const int h0 = h4 * RH;

    // 8 per-channel weights in registers (center tap excluded -> residual)
    float4 kv[9];
    #pragma unroll
    for (int i = 0; i < 9; ++i)
        if (i != 4) kv[i] = __ldg(&k[i * CG + cg]);

    const float4 zero = make_float4(0.f, 0.f, 0.f, 0.f);

    float4 acc[RH][RW];
    #pragma unroll
    for (int j = 0; j < RH; ++j)
        #pragma unroll
        for (int i = 0; i < RW; ++i)
            acc[j][i] = zero;

    // single 32-bit base index: (row h0-1, col w0-1, this cg)
    const int base = ((b * HH + h0 - 1) * WW + (w0 - 1)) * CG + cg;

    #pragma unroll
    for (int rr = 0; rr < RH + 2; ++rr) {
        const int r = h0 - 1 + rr;
        const bool hok = (r >= 0) & (r < HH);

        // branchless 4-wide column window; offsets are compile-time immediates
        float4 col[RW + 2];
        #pragma unroll
        for (int c = 0; c < RW + 2; ++c) {
            const int w = w0 - 1 + c;
            const bool ok = hok & (w >= 0) & (w < WW);
            col[c] = ok ? x[base + rr * ROWS + c * CG] : zero;
        }

        // dy = rr - 1 - j resolves at compile time after unrolling
        #pragma unroll
        for (int j = 0; j < RH; ++j) {
            const int dy = rr - 1 - j;
            if (dy < -1 || dy > 1) continue;   // compile-time prune
            #pragma unroll
            for (int i = 0; i < RW; ++i) {
                #pragma unroll
                for (int dx = -1; dx <= 1; ++dx) {
                    if (dy == 0 && dx == 0) {
                        // zero-weight center tap -> residual add
                        acc[j][i].x += col[i + 1].x;
                        acc[j][i].y += col[i + 1].y;
                        acc[j][i].z += col[i + 1].z;
                        acc[j][i].w += col[i + 1].w;
                        continue;
                    }
                    const float4 xv = col[i + 1 + dx];
                    const float4 wv = kv[(dy + 1) * 3 + (dx + 1)];
                    acc[j][i].x = fmaf(xv.x, wv.x, acc[j][i].x);
                    acc[j][i].y = fmaf(xv.y, wv.y, acc[j][i].y);
                    acc[j][i].z = fmaf(xv.z, wv.z, acc[j][i].z);
                    acc[j][i].w = fmaf(xv.w, wv.w, acc[j][i].w);
                }
            }
        }
    }

    // output base = (row h0, col w0) = base + one row + one col
    const int obase = base + ROWS + CG;
    #pragma unroll
    for (int j = 0; j < RH; ++j)
        #pragma unroll
        for (int i = 0; i < RW; ++i)
            out[obase + j * ROWS + i * CG] = acc[j][i];
}

extern "C" void kernel_launch(void* const* d_in, const int* in_sizes, int n_in,
                              void* d_out, int out_size)
{
    const float4* x = (const float4*)d_in[0];
    const float4* k = (const float4*)d_in[1];
    float4* out = (float4*)d_out;

    const int total = BH * (HH / RH) * (WW / RW) * CG;   // 802816 threads
    contour_kernel<<<total / 256, 256>>>(x, k, out);
}

// round 4
// speedup vs baseline: 1.5274x; 1.0883x over previous
#include <cuda_runtime.h>
#include <cuda_bf16.h>

// Depthwise 3x3 lateral conv (center tap zeroed) + residual add.
// x: [B,H,W,C] f32 NHWC, kernel: [3,3,C] f32. B=32,H=56,W=56,C=256.
// Register-blocked 4(h) x 2(w) per thread, one float4 channel-group.
// 32-bit base + immediate-offset addressing. Streaming (evict-first)
// stores keep x resident in L2 across graph replays. launch_bounds
// caps regs at 85 for 3 blocks/SM.

#define BH 32
#define HH 56
#define WW 56
#define CG 64            // 256 channels / 4
#define RH 4
#define RW 2
#define ROWS (WW * CG)   // float4 elements per image row = 3584

__global__ __launch_bounds__(256, 3) void contour_kernel(
    const float4* __restrict__ x,
    const float4* __restrict__ k,
    float4* __restrict__ out)
{
    const int gid = blockIdx.x * 256 + threadIdx.x;
    const int cg  = gid & (CG - 1);
    int t = gid >> 6;
    const int w2 = t % (WW / RW);  t /= (WW / RW);
    const int h4 = t % (HH / RH);
    const int b  = t / (HH / RH);
    const int w0 = w2 * RW;
    const int h0 = h4 * RH;

    // 8 per-channel weights in registers (center tap excluded -> residual)
    float4 kv[9];
    #pragma unroll
    for (int i = 0; i < 9; ++i)
        if (i != 4) kv[i] = __ldg(&k[i * CG + cg]);

    const float4 zero = make_float4(0.f, 0.f, 0.f, 0.f);

    float4 acc[RH][RW];
    #pragma unroll
    for (int j = 0; j < RH; ++j)
        #pragma unroll
        for (int i = 0; i < RW; ++i)
            acc[j][i] = zero;

    // single 32-bit base index: (row h0-1, col w0-1, this cg)
    const int base = ((b * HH + h0 - 1) * WW + (w0 - 1)) * CG + cg;

    #pragma unroll
    for (int rr = 0; rr < RH + 2; ++rr) {
        const int r = h0 - 1 + rr;
        const bool hok = (r >= 0) & (r < HH);

        // branchless 4-wide column window; offsets are compile-time immediates
        float4 col[RW + 2];
        #pragma unroll
        for (int c = 0; c < RW + 2; ++c) {
            const int w = w0 - 1 + c;
            const bool ok = hok & (w >= 0) & (w < WW);
            col[c] = ok ? x[base + rr * ROWS + c * CG] : zero;
        }

        // dy = rr - 1 - j resolves at compile time after unrolling
        #pragma unroll
        for (int j = 0; j < RH; ++j) {
            const int dy = rr - 1 - j;
            if (dy < -1 || dy > 1) continue;   // compile-time prune
            #pragma unroll
            for (int i = 0; i < RW; ++i) {
                #pragma unroll
                for (int dx = -1; dx <= 1; ++dx) {
                    if (dy == 0 && dx == 0) {
                        // zero-weight center tap -> residual add
                        acc[j][i].x += col[i + 1].x;
                        acc[j][i].y += col[i + 1].y;
                        acc[j][i].z += col[i + 1].z;
                        acc[j][i].w += col[i + 1].w;
                        continue;
                    }
                    const float4 xv = col[i + 1 + dx];
                    const float4 wv = kv[(dy + 1) * 3 + (dx + 1)];
                    acc[j][i].x = fmaf(xv.x, wv.x, acc[j][i].x);
                    acc[j][i].y = fmaf(xv.y, wv.y, acc[j][i].y);
                    acc[j][i].z = fmaf(xv.z, wv.z, acc[j][i].z);
                    acc[j][i].w = fmaf(xv.w, wv.w, acc[j][i].w);
                }
            }
        }
    }

    // output base = (row h0, col w0). Streaming stores: evict-first in L2
    // so the input tensor stays L2-resident across graph replays.
    const int obase = base + ROWS + CG;
    #pragma unroll
    for (int j = 0; j < RH; ++j)
        #pragma unroll
        for (int i = 0; i < RW; ++i)
            __stcs(&out[obase + j * ROWS + i * CG], acc[j][i]);
}

extern "C" void kernel_launch(void* const* d_in, const int* in_sizes, int n_in,
                              void* d_out, int out_size)
{
    const float4* x = (const float4*)d_in[0];
    const float4* k = (const float4*)d_in[1];
    float4* out = (float4*)d_out;

    const int total = BH * (HH / RH) * (WW / RW) * CG;   // 802816 threads
    contour_kernel<<<total / 256, 256>>>(x, k, out);
}